// round 8
// baseline (speedup 1.0000x reference)
#include <cuda_runtime.h>

#define GN 512
#define TBR 64          // tile rows
#define TBC 32          // tile cols
#define TD 8            // max temporal depth per launch
#define ROWS_P 82       // padded smem rows (region 80 + ring)
#define COLS_P 56       // float stride (conflict-free-ish for LDS.128 phases)
#define NGRP 12         // 4-column groups per region (48 cols)
#define NT 960          // 12 groups x 80 one-row strips -> 30 warps
#define TOTAL_STEPS 199

typedef unsigned long long u64;

__device__ __forceinline__ u64 PK(float a, float b) {
    u64 r; asm("mov.b64 %0,{%1,%2};" : "=l"(r) : "f"(a), "f"(b)); return r;
}
__device__ __forceinline__ void UNPK(u64 v, float& a, float& b) {
    asm("mov.b64 {%0,%1},%2;" : "=f"(a), "=f"(b) : "l"(v));
}
__device__ __forceinline__ u64 ADD2(u64 a, u64 b) {
    u64 d; asm("add.rn.f32x2 %0,%1,%2;" : "=l"(d) : "l"(a), "l"(b)); return d;
}
__device__ __forceinline__ u64 MUL2(u64 a, u64 b) {
    u64 d; asm("mul.rn.f32x2 %0,%1,%2;" : "=l"(d) : "l"(a), "l"(b)); return d;
}
__device__ __forceinline__ u64 FMA2(u64 a, u64 b, u64 c) {
    u64 d; asm("fma.rn.f32x2 %0,%1,%2,%3;" : "=l"(d) : "l"(a), "l"(b), "l"(c)); return d;
}

// new(i,j) = V(clamp(i,1,510), clamp(j,1,510)); state extended by clamp(.,0,511).
// 64x32 tiles -> 128 CTAs (one per SM). Full 80x48 region recomputed per step in a
// garbage-ringed smem buffer; contamination creeps 1 cell/step so the central 64x32
// stays exact for up to 8 steps. Thread = 4-col group x ONE row: 960 threads = 30
// warps/SM for latency hiding, float4 LDS/STS/STG + packed f32x2 math for slot
// efficiency. Row copies (0:=1, 511:=510) use suppress+duplicate across adjacent
// threads (suppressed thread never stores -> no race). Col specials are branchless.
template <int NSTEPS>
__global__ __launch_bounds__(NT) void adr_chunk(
    const float* __restrict__ in_state,
    float* __restrict__ frames,
    const float* __restrict__ k1p, const float* __restrict__ k2p,
    const float* __restrict__ a1p, const float* __restrict__ a2p)
{
    __shared__ __align__(16) float buf[2][ROWS_P][COLS_P];

    const float k1 = __ldg(k1p), k2 = __ldg(k2p);
    const float a1 = __ldg(a1p), a2 = __ldg(a2p);
    const float inv_k12 = 1.0f / (k1 + k2);
    const float inv_dx2 = 511.0f * 511.0f;
    const float inv_2dx = 255.5f;
    const float DTC = 1e-7f;

    const int by = blockIdx.y, bx = blockIdx.x;
    const int r0 = by * TBR - TD;
    const int c0 = bx * TBC - TD;
    const int g  = (int)threadIdx.x % NGRP;    // 4-col group 0..11
    const int ty = (int)threadIdx.x / NGRP;    // region row 0..79
    const int gj0 = c0 + 4 * g;
    const int sc  = 4 * g + 4;                 // smem col (16B aligned)

    const float kap = (gj0 < 256) ? k1 : k2;   // 4 | 256: never straddles
    const float al  = (gj0 < 256) ? a1 : a2;

    const float A1 = DTC * al * inv_dx2;
    const u64 cA1   = PK(A1, A1);
    const u64 cM4A1 = PK(-4.0f * A1, -4.0f * A1);
    const u64 cM1   = PK(-1.0f, -1.0f);
    const u64 cONE  = PK(1.0f, 1.0f);
    const u64 cI2   = PK(inv_2dx, inv_2dx);
    const u64 cMI2  = PK(-inv_2dx, -inv_2dx);
    const u64 cB1   = PK(DTC * kap, DTC * kap);

    const bool colC = (g >= 2) && (g <= 9);            // central 32 cols
    const bool rowC = (ty >= TD) && (ty <= TD + TBR - 1); // central rows 8..71
    const bool isI  = (gj0 == 252);
    const bool isL  = (gj0 == 0);
    const bool isR  = (gj0 == 508);
    const bool lastBy = (by == GN / TBR - 1);
    const bool supTop = (by == 0) && (ty == 8);     // nominal global row 0: wrong, suppress
    const bool fixTop = (by == 0) && (ty == 9);     // owns global row 1 -> dup into row 0
    const bool supBot = lastBy && (ty == 71);       // nominal global row 511: suppress
    const bool fixBot = lastBy && (ty == 70);       // owns global row 510 -> dup into 511
    const bool doStore = colC && rowC && !(supTop || supBot);

    auto pointPair = [&](u64 Tm, u64 Tc, u64 Tp, u64 L, u64 R) -> u64 {
        u64 sum  = ADD2(ADD2(Tm, Tp), ADD2(L, R));
        u64 lapc = FMA2(Tc, cM4A1, MUL2(sum, cA1));   // DT*al*lap
        u64 dxv  = FMA2(Tm, cM1, Tp);                  // Tp - Tm
        u64 dyv  = FMA2(L,  cM1, R);                   // R - L
        u64 P    = FMA2(dxv, cMI2, ADD2(Tc, cM1));     // (c-1) - T_x
        u64 Q    = FMA2(dyv, cI2,  cONE);              // T_y + 1
        u64 S    = FMA2(MUL2(Tc, Tc), P, MUL2(Tc, Q)); // c^2*P + c*Q
        return ADD2(Tc, FMA2(S, cB1, lapc));
    };

    // ---- load region: one row per thread; pad ring stays garbage ----
    {
        int gi = r0 + ty;
        int li = min(max(gi, 0), GN - 1);
        float4 v;
        if (gj0 >= 0 && gj0 + 3 < GN) {
            v = *(const float4*)&in_state[(size_t)li * GN + gj0];
        } else {
            int j0 = min(max(gj0 + 0, 0), GN - 1);
            int j1 = min(max(gj0 + 1, 0), GN - 1);
            int j2 = min(max(gj0 + 2, 0), GN - 1);
            int j3 = min(max(gj0 + 3, 0), GN - 1);
            v = make_float4(in_state[(size_t)li * GN + j0],
                            in_state[(size_t)li * GN + j1],
                            in_state[(size_t)li * GN + j2],
                            in_state[(size_t)li * GN + j3]);
        }
        *(float4*)&buf[0][ty + 1][sc] = v;
    }
    __syncthreads();

    float* const fr = frames + (ptrdiff_t)(r0 + ty) * GN + gj0;

    #pragma unroll
    for (int s = 0; s < NSTEPS; ++s) {
        const float (*A)[COLS_P] = buf[s & 1];
        float (*B)[COLS_P] = buf[(s & 1) ^ 1];
        const size_t fs = (size_t)s * (GN * GN);

        float4 Fm = *(const float4*)&A[ty + 0][sc];
        float4 Fc = *(const float4*)&A[ty + 1][sc];
        float4 Fp = *(const float4*)&A[ty + 2][sc];
        float TlS = A[ty + 1][sc - 1];
        float TrS = A[ty + 1][sc + 4];

        u64 Tm0 = PK(Fm.x, Fm.y), Tc0 = PK(Fc.x, Fc.y), Tp0 = PK(Fp.x, Fp.y);
        u64 Tm1 = PK(Fm.z, Fm.w), Tc1 = PK(Fc.z, Fc.w), Tp1 = PK(Fp.z, Fp.w);
        u64 L0 = PK(TlS, Fc.x);
        u64 M  = PK(Fc.y, Fc.z);      // R of pair0 == L of pair1
        u64 R1 = PK(Fc.w, TrS);
        u64 v0 = pointPair(Tm0, Tc0, Tp0, L0, M);
        u64 v1 = pointPair(Tm1, Tc1, Tp1, M, R1);

        float a, b;
        UNPK(v1, a, b);
        float ifv = fmaf(k1, TrS, k2 * Fc.z) * inv_k12;  // interface col 255 (prev state)
        b = isI ? ifv : b;
        b = isR ? a : b;                                  // col 511 := 510
        float c, d;
        UNPK(v0, c, d);
        c = isL ? d : c;                                  // col 0 := 1
        float4 V = make_float4(c, d, a, b);

        if (!(supTop || supBot)) *(float4*)&B[ty + 1][sc] = V;
        if (doStore) *(float4*)&fr[fs] = V;

        if (fixTop) {                 // global row 0 := row 1
            *(float4*)&B[9][sc] = V;  // region row 8
            if (colC) *(float4*)&frames[fs + gj0] = V;
        }
        if (fixBot) {                 // global row 511 := row 510
            *(float4*)&B[72][sc] = V; // region row 71
            if (colC) *(float4*)&frames[fs + (size_t)(GN - 1) * GN + gj0] = V;
        }
        __syncthreads();
    }
}

extern "C" void kernel_launch(void* const* d_in, const int* in_sizes, int n_in,
                              void* d_out, int out_size)
{
    (void)in_sizes; (void)n_in; (void)out_size;
    const float* u0 = (const float*)d_in[0];
    const float* k1 = (const float*)d_in[1];
    const float* k2 = (const float*)d_in[2];
    const float* a1 = (const float*)d_in[3];
    const float* a2 = (const float*)d_in[4];
    float* out = (float*)d_out;

    dim3 grid(GN / TBC, GN / TBR);   // 16 x 8 = 128 CTAs
    dim3 block(NT);

    int done = 0;
    const float* src = u0;
    while (done < TOTAL_STEPS) {
        int steps = TOTAL_STEPS - done;
        if (steps >= TD) {
            adr_chunk<TD><<<grid, block>>>(src, out + (size_t)done * GN * GN,
                                           k1, k2, a1, a2);
            steps = TD;
        } else {
            adr_chunk<TD - 1><<<grid, block>>>(src, out + (size_t)done * GN * GN,
                                               k1, k2, a1, a2);  // final 7-step chunk
        }
        src = out + (size_t)(done + steps - 1) * GN * GN;
        done += steps;
    }
}

// round 9
// speedup vs baseline: 1.1181x; 1.1181x over previous
#include <cuda_runtime.h>

#define GN 512
#define TBR 64          // tile rows
#define TBC 32          // tile cols
#define TD 8            // max temporal depth per launch
#define ROWS_P 82       // padded smem rows (region 80 + ring)
#define COLS_P 56       // float stride: 2-row offset 112 = 16 mod 32 -> conflict-free LDS.128
#define NGRP 12         // 4-column groups per region (48 cols)
#define NT 480          // 12 groups x 40 two-row strips
#define TOTAL_STEPS 199

typedef unsigned long long u64;

__device__ __forceinline__ u64 PK(float a, float b) {
    u64 r; asm("mov.b64 %0,{%1,%2};" : "=l"(r) : "f"(a), "f"(b)); return r;
}
__device__ __forceinline__ void UNPK(u64 v, float& a, float& b) {
    asm("mov.b64 {%0,%1},%2;" : "=f"(a), "=f"(b) : "l"(v));
}
__device__ __forceinline__ u64 ADD2(u64 a, u64 b) {
    u64 d; asm("add.rn.f32x2 %0,%1,%2;" : "=l"(d) : "l"(a), "l"(b)); return d;
}
__device__ __forceinline__ u64 MUL2(u64 a, u64 b) {
    u64 d; asm("mul.rn.f32x2 %0,%1,%2;" : "=l"(d) : "l"(a), "l"(b)); return d;
}
__device__ __forceinline__ u64 FMA2(u64 a, u64 b, u64 c) {
    u64 d; asm("fma.rn.f32x2 %0,%1,%2,%3;" : "=l"(d) : "l"(a), "l"(b), "l"(c)); return d;
}

// new(i,j) = V(clamp(i,1,510), clamp(j,1,510)); state extended by clamp(.,0,511).
// 64x32 tiles -> 128 CTAs (one per SM). Thread = 4-col group x 2-row strip.
// Step 0 is FUSED with the global load: each thread LDGs its 4 vertical float4s +
// 4 edge scalars (clamped coords = true extended state), computes step 0 in
// registers, and stores the RESULT to smem -- no separate load phase, no step-0
// LDS, one less barrier, and the garbage ring only starts eroding at step 1.
// Steps 1..NSTEPS-2 run the proven smem ping-pong; the LAST step skips its STS
// and final barrier (nobody reads it). Col specials branchless; row copies via
// same-thread overwrite (ty==4 owns global rows 0,1; ty==35 owns 510,511).
template <int NSTEPS>
__global__ __launch_bounds__(NT) void adr_chunk(
    const float* __restrict__ in_state,
    float* __restrict__ frames,
    const float* __restrict__ k1p, const float* __restrict__ k2p,
    const float* __restrict__ a1p, const float* __restrict__ a2p)
{
    __shared__ __align__(16) float buf[2][ROWS_P][COLS_P];

    const float k1 = __ldg(k1p), k2 = __ldg(k2p);
    const float a1 = __ldg(a1p), a2 = __ldg(a2p);
    const float inv_k12 = 1.0f / (k1 + k2);
    const float inv_dx2 = 511.0f * 511.0f;
    const float inv_2dx = 255.5f;
    const float DTC = 1e-7f;

    const int by = blockIdx.y, bx = blockIdx.x;
    const int r0 = by * TBR - TD;
    const int c0 = bx * TBC - TD;
    const int g  = (int)threadIdx.x % NGRP;    // 4-col group 0..11
    const int ty = (int)threadIdx.x / NGRP;    // strip 0..39 (2 rows)
    const int rbase = ty * 2;                  // first computed region row
    const int gj0 = c0 + 4 * g;
    const int sc  = 4 * g + 4;                 // smem col (16B aligned)

    const float kap = (gj0 < 256) ? k1 : k2;   // 4 | 256: never straddles
    const float al  = (gj0 < 256) ? a1 : a2;

    const float A1c = DTC * al * inv_dx2;
    const u64 cA1   = PK(A1c, A1c);
    const u64 cM4A1 = PK(-4.0f * A1c, -4.0f * A1c);
    const u64 cM1   = PK(-1.0f, -1.0f);
    const u64 cONE  = PK(1.0f, 1.0f);
    const u64 cI2   = PK(inv_2dx, inv_2dx);
    const u64 cMI2  = PK(-inv_2dx, -inv_2dx);
    const u64 cB1   = PK(DTC * kap, DTC * kap);

    const bool colC = (g >= 2) && (g <= 9);            // central 32 cols
    const bool rowC = (ty >= 4) && (ty <= 35);         // central 64 rows
    const bool storeC = colC && rowC;
    const bool isI  = (gj0 == 252);                    // group holding col 255
    const bool isL  = (gj0 == 0);
    const bool isR  = (gj0 == 508);                    // group holding col 511
    const bool topFix = (by == 0) && (ty == 4);            // global rows 0,1
    const bool botFix = (by == GN / TBR - 1) && (ty == 35); // global rows 510,511

    auto pointPair = [&](u64 Tm, u64 Tc, u64 Tp, u64 L, u64 R) -> u64 {
        u64 sum  = ADD2(ADD2(Tm, Tp), ADD2(L, R));
        u64 lapc = FMA2(Tc, cM4A1, MUL2(sum, cA1));   // DT*al*lap
        u64 dxv  = FMA2(Tm, cM1, Tp);                  // Tp - Tm
        u64 dyv  = FMA2(L,  cM1, R);                   // R - L
        u64 P    = FMA2(dxv, cMI2, ADD2(Tc, cM1));     // (c-1) - T_x
        u64 Q    = FMA2(dyv, cI2,  cONE);              // T_y + 1
        u64 S    = FMA2(MUL2(Tc, Tc), P, MUL2(Tc, Q)); // c^2*P + c*Q
        return ADD2(Tc, FMA2(S, cB1, lapc));
    };

    auto rowcalc = [&](float4 Fm, float4 Fc, float4 Fp, float TlS, float TrS,
                       u64& v0, u64& v1) {
        u64 Tm0 = PK(Fm.x, Fm.y), Tc0 = PK(Fc.x, Fc.y), Tp0 = PK(Fp.x, Fp.y);
        u64 Tm1 = PK(Fm.z, Fm.w), Tc1 = PK(Fc.z, Fc.w), Tp1 = PK(Fp.z, Fp.w);
        u64 L0 = PK(TlS, Fc.x);
        u64 M  = PK(Fc.y, Fc.z);      // R of pair0 == L of pair1
        u64 R1 = PK(Fc.w, TrS);
        v0 = pointPair(Tm0, Tc0, Tp0, L0, M);
        v1 = pointPair(Tm1, Tc1, Tp1, M, R1);
        float a, b;
        UNPK(v1, a, b);
        float ifv = fmaf(k1, TrS, k2 * Fc.z) * inv_k12;  // interface col 255
        b = isI ? ifv : b;
        b = isR ? a : b;                                  // col 511 := 510
        v1 = PK(a, b);
        UNPK(v0, a, b);
        a = isL ? b : a;                                  // col 0 := 1
        v0 = PK(a, b);
    };

    auto F4 = [](u64 v0, u64 v1) -> float4 {
        float a, b, c, d; UNPK(v0, a, b); UNPK(v1, c, d);
        return make_float4(a, b, c, d);
    };

    float* const fr0 = frames + (ptrdiff_t)(r0 + rbase) * GN + gj0;

    // ================= fused global load + STEP 0 =================
    {
        const bool canVec = (gj0 >= 0) && (gj0 + 3 < GN);
        const int j0 = min(max(gj0 + 0, 0), GN - 1);
        const int j1 = min(max(gj0 + 1, 0), GN - 1);
        const int j2 = min(max(gj0 + 2, 0), GN - 1);
        const int j3 = min(max(gj0 + 3, 0), GN - 1);
        const int jl = min(max(gj0 - 1, 0), GN - 1);
        const int jr = min(max(gj0 + 4, 0), GN - 1);

        auto ldrow = [&](int gi) -> float4 {
            int li = min(max(gi, 0), GN - 1);
            if (canVec) return *(const float4*)&in_state[(size_t)li * GN + gj0];
            return make_float4(in_state[(size_t)li * GN + j0],
                               in_state[(size_t)li * GN + j1],
                               in_state[(size_t)li * GN + j2],
                               in_state[(size_t)li * GN + j3]);
        };
        auto lded = [&](int gi, int jj) -> float {
            int li = min(max(gi, 0), GN - 1);
            return in_state[(size_t)li * GN + jj];
        };

        // global rows feeding region rows rbase, rbase+1
        float4 Fm = ldrow(r0 + rbase - 1);
        float4 F1 = ldrow(r0 + rbase);
        float4 F2 = ldrow(r0 + rbase + 1);
        float4 F3 = ldrow(r0 + rbase + 2);
        float TlA = lded(r0 + rbase,     jl), TrA = lded(r0 + rbase,     jr);
        float TlB = lded(r0 + rbase + 1, jl), TrB = lded(r0 + rbase + 1, jr);

        u64 a0, a1v, b0, b1v;
        rowcalc(Fm, F1, F2, TlA, TrA, a0, a1v);   // region row rbase
        rowcalc(F1, F2, F3, TlB, TrB, b0, b1v);   // region row rbase+1
        float4 VA = F4(a0, a1v);
        float4 VB = F4(b0, b1v);

        *(float4*)&buf[0][rbase + 1][sc] = VA;
        *(float4*)&buf[0][rbase + 2][sc] = VB;
        if (storeC) {
            *(float4*)&fr0[0]  = VA;
            *(float4*)&fr0[GN] = VB;
        }
        if (topFix) {               // global row 0 := row 1
            *(float4*)&buf[0][9][sc] = VB;
            if (colC) *(float4*)&frames[gj0] = VB;
        }
        if (botFix) {               // global row 511 := row 510
            *(float4*)&buf[0][72][sc] = VA;
            if (colC) *(float4*)&frames[(size_t)(GN - 1) * GN + gj0] = VA;
        }
    }
    __syncthreads();

    // ================= steps 1 .. NSTEPS-1 (smem ping-pong) =================
    #pragma unroll
    for (int s = 1; s < NSTEPS; ++s) {
        const float (*A)[COLS_P] = buf[(s + 1) & 1];
        float (*B)[COLS_P] = buf[s & 1];
        float* f0 = fr0 + (size_t)s * (GN * GN);
        const bool last = (s == NSTEPS - 1);

        float4 F0 = *(const float4*)&A[rbase + 0][sc];
        float4 F1 = *(const float4*)&A[rbase + 1][sc];
        float4 F2 = *(const float4*)&A[rbase + 2][sc];
        float4 F3 = *(const float4*)&A[rbase + 3][sc];
        float TlA = A[rbase + 1][sc - 1], TrA = A[rbase + 1][sc + 4];
        float TlB = A[rbase + 2][sc - 1], TrB = A[rbase + 2][sc + 4];

        u64 a0, a1v, b0, b1v;
        rowcalc(F0, F1, F2, TlA, TrA, a0, a1v);   // region row rbase
        rowcalc(F1, F2, F3, TlB, TrB, b0, b1v);   // region row rbase+1

        float4 VA = F4(a0, a1v);
        float4 VB = F4(b0, b1v);
        if (!last) {
            *(float4*)&B[rbase + 1][sc] = VA;
            *(float4*)&B[rbase + 2][sc] = VB;
        }
        if (storeC) {
            *(float4*)&f0[0]  = VA;
            *(float4*)&f0[GN] = VB;
        }
        if (topFix) {               // global row 0 := row 1
            if (!last) *(float4*)&B[9][sc] = VB;
            if (colC) *(float4*)&frames[(size_t)s * (GN * GN) + gj0] = VB;
        }
        if (botFix) {               // global row 511 := row 510
            if (!last) *(float4*)&B[72][sc] = VA;
            if (colC) *(float4*)&frames[(size_t)s * (GN * GN) + (size_t)(GN - 1) * GN + gj0] = VA;
        }
        if (!last) __syncthreads();
    }
}

extern "C" void kernel_launch(void* const* d_in, const int* in_sizes, int n_in,
                              void* d_out, int out_size)
{
    (void)in_sizes; (void)n_in; (void)out_size;
    const float* u0 = (const float*)d_in[0];
    const float* k1 = (const float*)d_in[1];
    const float* k2 = (const float*)d_in[2];
    const float* a1 = (const float*)d_in[3];
    const float* a2 = (const float*)d_in[4];
    float* out = (float*)d_out;

    dim3 grid(GN / TBC, GN / TBR);   // 16 x 8 = 128 CTAs
    dim3 block(NT);

    int done = 0;
    const float* src = u0;
    while (done < TOTAL_STEPS) {
        int steps = TOTAL_STEPS - done;
        if (steps >= TD) {
            adr_chunk<TD><<<grid, block>>>(src, out + (size_t)done * GN * GN,
                                           k1, k2, a1, a2);
            steps = TD;
        } else {
            adr_chunk<TD - 1><<<grid, block>>>(src, out + (size_t)done * GN * GN,
                                               k1, k2, a1, a2);  // final 7-step chunk
        }
        src = out + (size_t)(done + steps - 1) * GN * GN;
        done += steps;
    }
}